// round 10
// baseline (speedup 1.0000x reference)
#include <cuda_runtime.h>
#include <math.h>

#define BB 2
#define PP 8192
#define KK 20
#define NBIN 256
#define ZLO 1.0f
#define ZSPAN 60.0f
#define INVBINW (NBIN / ZSPAN)
#define LBUF 64
#define CTHRESH 40

// 3D count grid (threshold oracle): 1.5 m cells over [-10,10]^2 x [1,61]
#define G2X 14
#define G2Y 14
#define G2Z 40
#define NC2 (G2X * G2Y * G2Z)
#define C2 1.5f
#define INVC2 (1.0f / 1.5f)
#define OXC (-10.0f)
#define OYC (-10.0f)
#define OZC (1.0f)

__device__ double g_acc[2];
__device__ unsigned g_done;
__device__ int g_hist[8][NBIN];        // [set*2 + (0=db,1=query)]
__device__ int g_offs[8][NBIN + 1];
__device__ int g_curs[8][NBIN];
__device__ int g_cnt2[4 * NC2];
__device__ float4 g_dbp[4][PP];        // z-binned db points (x,y,z, idx bits)
__device__ float4 g_qp[4][PP];         // z-binned transformed queries

#define CHAIN_INSERT(keys, x)                                                   \
    do {                                                                        \
        float tt0 = keys[4], tt1 = keys[9], tt2 = keys[14], tt3 = keys[19];     \
        int sel_ = 0; float bv_ = tt0;                                          \
        if (tt1 > bv_) { bv_ = tt1; sel_ = 1; }                                 \
        if (tt2 > bv_) { bv_ = tt2; sel_ = 2; }                                 \
        if (tt3 > bv_) { bv_ = tt3; sel_ = 3; }                                 \
        float x0_ = (sel_ == 0) ? (x) : 3.3e38f;                                \
        float x1_ = (sel_ == 1) ? (x) : 3.3e38f;                                \
        float x2_ = (sel_ == 2) ? (x) : 3.3e38f;                                \
        float x3_ = (sel_ == 3) ? (x) : 3.3e38f;                                \
        _Pragma("unroll")                                                       \
        for (int k_ = 0; k_ < 5; k_++) {                                        \
            float lo_ = fminf(x0_, keys[k_]); x0_ = fmaxf(x0_, keys[k_]); keys[k_] = lo_; } \
        _Pragma("unroll")                                                       \
        for (int k_ = 5; k_ < 10; k_++) {                                       \
            float lo_ = fminf(x1_, keys[k_]); x1_ = fmaxf(x1_, keys[k_]); keys[k_] = lo_; } \
        _Pragma("unroll")                                                       \
        for (int k_ = 10; k_ < 15; k_++) {                                      \
            float lo_ = fminf(x2_, keys[k_]); x2_ = fmaxf(x2_, keys[k_]); keys[k_] = lo_; } \
        _Pragma("unroll")                                                       \
        for (int k_ = 15; k_ < 20; k_++) {                                      \
            float lo_ = fminf(x3_, keys[k_]); x3_ = fmaxf(x3_, keys[k_]); keys[k_] = lo_; } \
    } while (0)

__device__ __forceinline__ int zbin(float z) {
    return min(NBIN - 1, max(0, (int)floorf((z - ZLO) * INVBINW)));
}
__device__ __forceinline__ void cell2_coords(float x, float y, float z,
                                             int& ix, int& iy, int& iz) {
    ix = min(G2X - 1, max(0, (int)floorf((x - OXC) * INVC2)));
    iy = min(G2Y - 1, max(0, (int)floorf((y - OYC) * INVC2)));
    iz = min(G2Z - 1, max(0, (int)floorf((z - OZC) * INVC2)));
}

__global__ void init_kernel() {
    int i = blockIdx.x * blockDim.x + threadIdx.x;
    if (i == 0) { g_acc[0] = 0.0; g_acc[1] = 0.0; g_done = 0u; }
    if (i < 8 * NBIN) ((int*)g_hist)[i] = 0;
    for (int j = i; j < 4 * NC2; j += gridDim.x * blockDim.x) g_cnt2[j] = 0;
}

// Fused: db z-hist + db count-grid + query transform & z-hist.
__global__ void build_kernel(const float* __restrict__ xyz1, const float* __restrict__ xyz2,
                             const float* __restrict__ R12, const float* __restrict__ t12,
                             const float* __restrict__ R21, const float* __restrict__ t21,
                             const int* __restrict__ npts1, const int* __restrict__ npts2) {
    const int s = blockIdx.y;
    const int gi = blockIdx.x * blockDim.x + threadIdx.x;
    const int b = gi >> 13;
    const int i = gi & (PP - 1);
    const int set = s * BB + b;
    const float* dbsrc = s ? xyz1 : xyz2;
    const int ldb = (s ? npts1 : npts2)[b];
    if (i < ldb) {
        float x = dbsrc[3 * gi + 0], y = dbsrc[3 * gi + 1], z = dbsrc[3 * gi + 2];
        atomicAdd(&g_hist[set * 2][zbin(z)], 1);
        int ix, iy, iz;
        cell2_coords(x, y, z, ix, iy, iz);
        atomicAdd(&g_cnt2[set * NC2 + (iz * G2Y + iy) * G2X + ix], 1);
    }
    const float* qsrc = s ? xyz2 : xyz1;
    const int lq = (s ? npts2 : npts1)[b];
    if (i < lq) {
        const float* Rm = (s ? R21 : R12) + b * 9;
        const float* tv = (s ? t21 : t12) + b * 3;
        float ux = qsrc[3 * gi + 0] - tv[0];
        float uy = qsrc[3 * gi + 1] - tv[1];
        float uz = qsrc[3 * gi + 2] - tv[2];
        float qpz = fmaf(Rm[2], ux, fmaf(Rm[5], uy, Rm[8] * uz));
        atomicAdd(&g_hist[set * 2 + 1][zbin(qpz)], 1);
    }
}

__global__ void scan_kernel() {
    __shared__ int sv[NBIN];
    const int t = threadIdx.x;
    for (int a = 0; a < 8; a++) {
        int v = g_hist[a][t];
        sv[t] = v;
        __syncthreads();
        for (int o = 1; o < NBIN; o <<= 1) {
            int x = (t >= o) ? sv[t - o] : 0;
            __syncthreads();
            sv[t] += x;
            __syncthreads();
        }
        g_offs[a][t + 1] = sv[t];
        g_curs[a][t] = sv[t] - v;
        if (t == 0) g_offs[a][0] = 0;
        __syncthreads();
    }
}

__global__ void scatter_kernel(const float* __restrict__ xyz1, const float* __restrict__ xyz2,
                               const float* __restrict__ R12, const float* __restrict__ t12,
                               const float* __restrict__ R21, const float* __restrict__ t21,
                               const int* __restrict__ npts1, const int* __restrict__ npts2) {
    const int s = blockIdx.y;
    const int gi = blockIdx.x * blockDim.x + threadIdx.x;
    const int b = gi >> 13;
    const int i = gi & (PP - 1);
    const int set = s * BB + b;
    const float* dbsrc = s ? xyz1 : xyz2;
    const int ldb = (s ? npts1 : npts2)[b];
    if (i < ldb) {
        float x = dbsrc[3 * gi + 0], y = dbsrc[3 * gi + 1], z = dbsrc[3 * gi + 2];
        int pos = atomicAdd(&g_curs[set * 2][zbin(z)], 1);
        g_dbp[set][pos] = make_float4(x, y, z, __int_as_float(i));
    }
    const float* qsrc = s ? xyz2 : xyz1;
    const int lq = (s ? npts2 : npts1)[b];
    if (i < lq) {
        const float* Rm = (s ? R21 : R12) + b * 9;
        const float* tv = (s ? t21 : t12) + b * 3;
        float ux = qsrc[3 * gi + 0] - tv[0];
        float uy = qsrc[3 * gi + 1] - tv[1];
        float uz = qsrc[3 * gi + 2] - tv[2];
        float qpx = fmaf(Rm[0], ux, fmaf(Rm[3], uy, Rm[6] * uz));
        float qpy = fmaf(Rm[1], ux, fmaf(Rm[4], uy, Rm[7] * uz));
        float qpz = fmaf(Rm[2], ux, fmaf(Rm[5], uy, Rm[8] * uz));
        int pos = atomicAdd(&g_curs[set * 2 + 1][zbin(qpz)], 1);
        g_qp[set][pos] = make_float4(qpx, qpy, qpz, __int_as_float(i));
    }
}

// Warp = 32 z-sorted queries; oracle threshold; single flat span scan (pipelined);
// ballot-synchronized compacts; exact epilogue.
__global__ __launch_bounds__(256) void query_kernel(
    const float* __restrict__ xyz1, const float* __restrict__ hsv1,
    const float* __restrict__ normal1, const float* __restrict__ nres1,
    const float* __restrict__ xyz2, const float* __restrict__ hsv2,
    const float* __restrict__ normal2, const float* __restrict__ nres2,
    const float* __restrict__ R12, const float* __restrict__ t12,
    const float* __restrict__ R21, const float* __restrict__ t21,
    const int* __restrict__ npts1, const int* __restrict__ npts2,
    float* __restrict__ out)
{
    const int set = blockIdx.y;
    const int s = set >> 1, b = set & 1;
    const int lane = threadIdx.x & 31;
    const int wid = threadIdx.x >> 5;
    const int boff = b * PP;

    const float* xq   = s ? xyz2 : xyz1;
    const float* hq   = s ? hsv2 : hsv1;
    const float* nq   = s ? normal2 : normal1;
    const float* rq   = s ? nres2 : nres1;
    const float* xdbr = s ? xyz1 : xyz2;
    const float* ndbr = s ? normal1 : normal2;
    const float* hdb  = s ? hsv1 : hsv2;
    const float* rdb  = s ? nres1 : nres2;
    const float* Rm   = (s ? R21 : R12) + b * 9;
    const int lq = (s ? npts2 : npts1)[b];

    float sum = 0.f;
    const int base = (blockIdx.x * 8 + wid) * 32;

    if (base < lq) {
        const int pos = base + lane;
        const bool act = pos < lq;
        float4 qr = g_qp[set][act ? pos : base];
        const float qpx = qr.x, qpy = qr.y, qpz = qr.z;
        const int iq = __float_as_int(qr.w);

        // Oracle: expand count-grid cube until >= KK points; T2 = corner dist^2
        // (true upper bound on d20^2 -> exact pruning).
        float T2 = 3.0e38f;
        {
            int cx, cy, cz;
            cell2_coords(qpx, qpy, qpz, cx, cy, cz);
            const int* cnt2 = g_cnt2 + set * NC2;
            for (int m = 1; m <= 3; m++) {
                int xlo = max(cx - m, 0), xhi = min(cx + m, G2X - 1);
                int ylo = max(cy - m, 0), yhi = min(cy + m, G2Y - 1);
                int zlo = max(cz - m, 0), zhi = min(cz + m, G2Z - 1);
                int cnt = 0;
                for (int z = zlo; z <= zhi; z++)
                    for (int y = ylo; y <= yhi; y++) {
                        int rb = (z * G2Y + y) * G2X;
                        for (int x = xlo; x <= xhi; x++) cnt += cnt2[rb + x];
                    }
                if (cnt >= KK) {
                    float lx = OXC + (float)xlo * C2, hx2 = OXC + (float)(xhi + 1) * C2;
                    float ly = OYC + (float)ylo * C2, hy2 = OYC + (float)(yhi + 1) * C2;
                    float lz = OZC + (float)zlo * C2, hz2 = OZC + (float)(zhi + 1) * C2;
                    float ax = fmaxf(fabsf(qpx - lx), fabsf(qpx - hx2));
                    float ay = fmaxf(fabsf(qpy - ly), fabsf(qpy - hy2));
                    float az = fmaxf(fabsf(qpz - lz), fabsf(qpz - hz2));
                    T2 = fmaf(ax, ax, fmaf(ay, ay, az * az)) * 1.0002f;
                    break;
                }
            }
        }

        float keys[KK];
#pragma unroll
        for (int k = 0; k < KK; k++) keys[k] = 3.0e38f;
        float thr_l = act ? T2 : -1.0f;
        int cnt = 0;
        unsigned lbuf[LBUF];

        auto compact = [&]() {
            for (int e = 0; e < cnt; ++e) {
                float xk = __uint_as_float(lbuf[e]);
                CHAIN_INSERT(keys, xk);
            }
            cnt = 0;
            float tail = fmaxf(fmaxf(keys[4], keys[9]), fmaxf(keys[14], keys[19]));
            if (act) thr_l = fminf(thr_l, tail * 1.002f);
        };

        // Warp-uniform contiguous span from per-lane windows (clamped sqrt).
        float r = sqrtf(fminf(T2, 3600.0f));
        int blo = act ? zbin(qpz - r) : NBIN - 1;
        int bhi = act ? zbin(qpz + r) : 0;
#pragma unroll
        for (int o = 16; o; o >>= 1) {
            blo = min(blo, __shfl_xor_sync(0xffffffffu, blo, o));
            bhi = max(bhi, __shfl_xor_sync(0xffffffffu, bhi, o));
        }
        const int dbarr = set * 2;
        const int j0 = g_offs[dbarr][blo];
        const int j1 = g_offs[dbarr][bhi + 1];
        const float4* __restrict__ dbp = g_dbp[set];

        for (int jb = j0; jb < j1; jb += 16) {
            const int je = min(jb + 16, j1);
#pragma unroll 4
            for (int j = jb; j < je; ++j) {
                float4 p = dbp[j];                 // warp-uniform addr: broadcast
                float dx = qpx - p.x, dy = qpy - p.y, dz = qpz - p.z;
                float d2 = fmaf(dx, dx, fmaf(dy, dy, dz * dz));
                if (d2 < thr_l) {
                    unsigned key = (__float_as_uint(d2) & 0xFFFFE000u)
                                 | (unsigned)__float_as_int(p.w);
                    if (cnt < LBUF) lbuf[cnt++] = key;
                    else { float xk = __uint_as_float(key); CHAIN_INSERT(keys, xk); }
                }
            }
            if (__ballot_sync(0xffffffffu, cnt >= CTHRESH)) compact();
        }
        compact();

        // Exact epilogue over winners.
        if (act) {
            const int qi = boff + iq;
            const float qz_own = xq[3 * qi + 2];
            float ell = fmaxf(0.015f * (qz_own - 10.0f), 0.15f);
            float inv_ls = 1.0f / (ell * ell);
            float hx = hq[3 * qi + 0], hy = hq[3 * qi + 1], hz = hq[3 * qi + 2];
            float nxr = nq[3 * qi + 0], nyr = nq[3 * qi + 1], nzr = nq[3 * qi + 2];
            float npx = fmaf(Rm[0], nxr, fmaf(Rm[3], nyr, Rm[6] * nzr));
            float npy = fmaf(Rm[1], nxr, fmaf(Rm[4], nyr, Rm[7] * nzr));
            float npz = fmaf(Rm[2], nxr, fmaf(Rm[5], nyr, Rm[8] * nzr));
            float rqv = rq[qi];
#pragma unroll
            for (int k = 0; k < KK; k++) {
                if (keys[k] < 1.0e30f) {
                    int idx = (int)(__float_as_uint(keys[k]) & 0x1FFFu);
                    int g3 = 3 * (boff + idx);
                    float dx = qpx - xdbr[g3 + 0];
                    float dy = qpy - xdbr[g3 + 1];
                    float dz = qpz - xdbr[g3 + 2];
                    float d2 = fmaf(dx, dx, fmaf(dy, dy, dz * dz));
                    float ndot = fmaf(npx, ndbr[g3 + 0],
                                      fmaf(npy, ndbr[g3 + 1], npz * ndbr[g3 + 2]));
                    float chx = hx - hdb[g3 + 0];
                    float chy = hy - hdb[g3 + 1];
                    float chz = hz - hdb[g3 + 2];
                    float cd = sqrtf(fmaf(chx, chx, fmaf(chy, chy, chz * chz)) + 1e-12f);
                    float rk = rdb[boff + idx];
                    float alpha = 0.2f / (0.1f + rqv + rk);
                    float nk = fmaxf(ndot * alpha, 0.0f);
                    sum += __expf(-(d2 * inv_ls + cd * 5.0f)) * nk;
                }
            }
        }
    }

#pragma unroll
    for (int o = 16; o > 0; o >>= 1) sum += __shfl_down_sync(0xffffffffu, sum, o);
    __shared__ float wsum[8];
    if (lane == 0) wsum[wid] = sum;
    __syncthreads();
    if (threadIdx.x == 0) {
        float bs = 0.f;
#pragma unroll
        for (int w2 = 0; w2 < 8; w2++) bs += wsum[w2];
        atomicAdd(&g_acc[s], (double)bs);
        __threadfence();
        unsigned done = atomicAdd(&g_done, 1u);
        if (done == (unsigned)(gridDim.x * gridDim.y) - 1u) {
            double s1 = (double)npts1[0] + (double)npts1[1];
            double s2 = (double)npts2[0] + (double)npts2[1];
            double k1 = g_acc[0] / (s1 * (double)KK);
            double k2 = g_acc[1] / (s2 * (double)KK);
            out[0] = (float)(0.5 * (k1 + k2));
        }
    }
}

extern "C" void kernel_launch(void* const* d_in, const int* in_sizes, int n_in,
                              void* d_out, int out_size) {
    const float* xyz1    = (const float*)d_in[0];
    const float* xyz2    = (const float*)d_in[1];
    const float* hsv1    = (const float*)d_in[2];
    const float* hsv2    = (const float*)d_in[3];
    const float* normal1 = (const float*)d_in[4];
    const float* normal2 = (const float*)d_in[5];
    const float* nres1   = (const float*)d_in[6];
    const float* nres2   = (const float*)d_in[7];
    const float* R12     = (const float*)d_in[8];
    const float* t12     = (const float*)d_in[9];
    const float* R21     = (const float*)d_in[10];
    const float* t21     = (const float*)d_in[11];
    const int*   npts1   = (const int*)d_in[12];
    const int*   npts2   = (const int*)d_in[13];
    float* out = (float*)d_out;

    init_kernel<<<33, 1024>>>();
    dim3 bgrid(BB * PP / 256, 2);
    build_kernel<<<bgrid, 256>>>(xyz1, xyz2, R12, t12, R21, t21, npts1, npts2);
    scan_kernel<<<1, NBIN>>>();
    scatter_kernel<<<bgrid, 256>>>(xyz1, xyz2, R12, t12, R21, t21, npts1, npts2);
    dim3 qgrid(32, 4);
    query_kernel<<<qgrid, 256>>>(xyz1, hsv1, normal1, nres1,
                                 xyz2, hsv2, normal2, nres2,
                                 R12, t12, R21, t21, npts1, npts2, out);
}

// round 11
// speedup vs baseline: 6.1243x; 6.1243x over previous
#include <cuda_runtime.h>
#include <math.h>

#define BB 2
#define PP 8192
#define KK 20
#define NBIN 128
#define ZLO 1.0f
#define ZSPAN 60.0f
#define INVBINW (NBIN / ZSPAN)
#define BINW (ZSPAN / NBIN)
#define DCAP2 9.0f      // 3 m search-radius cap (dropped terms < 4e-7 each, see theory)
#define LBUF 64
#define CTHRESH 32

__device__ double g_acc[2];
__device__ unsigned g_done;
__device__ int g_hist[8][NBIN];        // [set*2 + (0=db,1=query)]
__device__ int g_offs[8][NBIN + 1];
__device__ int g_curs[8][NBIN];
__device__ float4 g_dbp[4][PP];        // z-binned db points (x,y,z, idx bits)
__device__ float4 g_qp[4][PP];         // z-binned transformed queries

// Insert packed key x into 4 sorted chains of 5 (tails at 4,9,14,19).
#define CHAIN_INSERT(keys, x)                                                   \
    do {                                                                        \
        float tt0 = keys[4], tt1 = keys[9], tt2 = keys[14], tt3 = keys[19];     \
        int sel_ = 0; float bv_ = tt0;                                          \
        if (tt1 > bv_) { bv_ = tt1; sel_ = 1; }                                 \
        if (tt2 > bv_) { bv_ = tt2; sel_ = 2; }                                 \
        if (tt3 > bv_) { bv_ = tt3; sel_ = 3; }                                 \
        float x0_ = (sel_ == 0) ? (x) : 3.3e38f;                                \
        float x1_ = (sel_ == 1) ? (x) : 3.3e38f;                                \
        float x2_ = (sel_ == 2) ? (x) : 3.3e38f;                                \
        float x3_ = (sel_ == 3) ? (x) : 3.3e38f;                                \
        _Pragma("unroll")                                                       \
        for (int k_ = 0; k_ < 5; k_++) {                                        \
            float lo_ = fminf(x0_, keys[k_]); x0_ = fmaxf(x0_, keys[k_]); keys[k_] = lo_; } \
        _Pragma("unroll")                                                       \
        for (int k_ = 5; k_ < 10; k_++) {                                       \
            float lo_ = fminf(x1_, keys[k_]); x1_ = fmaxf(x1_, keys[k_]); keys[k_] = lo_; } \
        _Pragma("unroll")                                                       \
        for (int k_ = 10; k_ < 15; k_++) {                                      \
            float lo_ = fminf(x2_, keys[k_]); x2_ = fmaxf(x2_, keys[k_]); keys[k_] = lo_; } \
        _Pragma("unroll")                                                       \
        for (int k_ = 15; k_ < 20; k_++) {                                      \
            float lo_ = fminf(x3_, keys[k_]); x3_ = fmaxf(x3_, keys[k_]); keys[k_] = lo_; } \
    } while (0)

__device__ __forceinline__ int zbin(float z) {
    return min(NBIN - 1, max(0, (int)floorf((z - ZLO) * INVBINW)));
}

__global__ void init_kernel() {
    int i = blockIdx.x * blockDim.x + threadIdx.x;
    if (i == 0) { g_acc[0] = 0.0; g_acc[1] = 0.0; g_done = 0u; }
    if (i < 8 * NBIN) ((int*)g_hist)[i] = 0;
}

// Histogram db points (raw z) and queries (q'z) per (side,batch) set.
__global__ void hist_kernel(const float* __restrict__ xyz1, const float* __restrict__ xyz2,
                            const float* __restrict__ R12, const float* __restrict__ t12,
                            const float* __restrict__ R21, const float* __restrict__ t21,
                            const int* __restrict__ npts1, const int* __restrict__ npts2) {
    const int s = blockIdx.y;
    const int gi = blockIdx.x * blockDim.x + threadIdx.x;
    const int b = gi >> 13;
    const int i = gi & (PP - 1);
    const int set = s * BB + b;
    const float* dbsrc = s ? xyz1 : xyz2;
    const int ldb = (s ? npts1 : npts2)[b];
    if (i < ldb)
        atomicAdd(&g_hist[set * 2][zbin(dbsrc[3 * gi + 2])], 1);
    const float* qsrc = s ? xyz2 : xyz1;
    const int lq = (s ? npts2 : npts1)[b];
    if (i < lq) {
        const float* Rm = (s ? R21 : R12) + b * 9;
        const float* tv = (s ? t21 : t12) + b * 3;
        float ux = qsrc[3 * gi + 0] - tv[0];
        float uy = qsrc[3 * gi + 1] - tv[1];
        float uz = qsrc[3 * gi + 2] - tv[2];
        float qpz = fmaf(Rm[2], ux, fmaf(Rm[5], uy, Rm[8] * uz));
        atomicAdd(&g_hist[set * 2 + 1][zbin(qpz)], 1);
    }
}

// Prefix-sum all 8 histograms; write offsets + scatter cursors.
__global__ void scan_kernel() {
    __shared__ int sv[NBIN];
    const int t = threadIdx.x;
    for (int a = 0; a < 8; a++) {
        int v = g_hist[a][t];
        sv[t] = v;
        __syncthreads();
        for (int o = 1; o < NBIN; o <<= 1) {
            int x = (t >= o) ? sv[t - o] : 0;
            __syncthreads();
            sv[t] += x;
            __syncthreads();
        }
        g_offs[a][t + 1] = sv[t];
        g_curs[a][t] = sv[t] - v;
        if (t == 0) g_offs[a][0] = 0;
        __syncthreads();
    }
}

// Scatter db points and transformed queries into bin-sorted arrays.
__global__ void scatter_kernel(const float* __restrict__ xyz1, const float* __restrict__ xyz2,
                               const float* __restrict__ R12, const float* __restrict__ t12,
                               const float* __restrict__ R21, const float* __restrict__ t21,
                               const int* __restrict__ npts1, const int* __restrict__ npts2) {
    const int s = blockIdx.y;
    const int gi = blockIdx.x * blockDim.x + threadIdx.x;
    const int b = gi >> 13;
    const int i = gi & (PP - 1);
    const int set = s * BB + b;
    const float* dbsrc = s ? xyz1 : xyz2;
    const int ldb = (s ? npts1 : npts2)[b];
    if (i < ldb) {
        float x = dbsrc[3 * gi + 0], y = dbsrc[3 * gi + 1], z = dbsrc[3 * gi + 2];
        int pos = atomicAdd(&g_curs[set * 2][zbin(z)], 1);
        g_dbp[set][pos] = make_float4(x, y, z, __int_as_float(i));
    }
    const float* qsrc = s ? xyz2 : xyz1;
    const int lq = (s ? npts2 : npts1)[b];
    if (i < lq) {
        const float* Rm = (s ? R21 : R12) + b * 9;
        const float* tv = (s ? t21 : t12) + b * 3;
        float ux = qsrc[3 * gi + 0] - tv[0];
        float uy = qsrc[3 * gi + 1] - tv[1];
        float uz = qsrc[3 * gi + 2] - tv[2];
        float qpx = fmaf(Rm[0], ux, fmaf(Rm[3], uy, Rm[6] * uz));
        float qpy = fmaf(Rm[1], ux, fmaf(Rm[4], uy, Rm[7] * uz));
        float qpz = fmaf(Rm[2], ux, fmaf(Rm[5], uy, Rm[8] * uz));
        int pos = atomicAdd(&g_curs[set * 2 + 1][zbin(qpz)], 1);
        g_qp[set][pos] = make_float4(qpx, qpy, qpz, __int_as_float(i));
    }
}

// Warp = 32 z-sorted queries; outward bin walk with ballot stop; local-buffer
// accepts with guarded warp-synchronized compaction; exact epilogue.
__global__ __launch_bounds__(256) void query_kernel(
    const float* __restrict__ xyz1, const float* __restrict__ hsv1,
    const float* __restrict__ normal1, const float* __restrict__ nres1,
    const float* __restrict__ xyz2, const float* __restrict__ hsv2,
    const float* __restrict__ normal2, const float* __restrict__ nres2,
    const float* __restrict__ R12, const float* __restrict__ t12,
    const float* __restrict__ R21, const float* __restrict__ t21,
    const int* __restrict__ npts1, const int* __restrict__ npts2,
    float* __restrict__ out)
{
    const int set = blockIdx.y;
    const int s = set >> 1, b = set & 1;
    const int lane = threadIdx.x & 31;
    const int wid = threadIdx.x >> 5;
    const int boff = b * PP;

    const float* xq   = s ? xyz2 : xyz1;
    const float* hq   = s ? hsv2 : hsv1;
    const float* nq   = s ? normal2 : normal1;
    const float* rq   = s ? nres2 : nres1;
    const float* xdbr = s ? xyz1 : xyz2;
    const float* ndbr = s ? normal1 : normal2;
    const float* hdb  = s ? hsv1 : hsv2;
    const float* rdb  = s ? nres1 : nres2;
    const float* Rm   = (s ? R21 : R12) + b * 9;
    const int lq = (s ? npts2 : npts1)[b];

    float sum = 0.f;
    const int base = (blockIdx.x * 8 + wid) * 32;

    if (base < lq) {
        const int pos = base + lane;
        const bool act = pos < lq;
        float4 qr = g_qp[set][act ? pos : base];
        const float qpx = qr.x, qpy = qr.y, qpz = qr.z;
        const int iq = __float_as_int(qr.w);

        float keys[KK];
#pragma unroll
        for (int k = 0; k < KK; k++) keys[k] = 3.0e38f;
        float thr_l = act ? DCAP2 : -1.0f;
        int cnt = 0;
        unsigned lbuf[LBUF];   // local memory candidate buffer

        auto compact = [&]() {
            float tail = fmaxf(fmaxf(keys[4], keys[9]), fmaxf(keys[14], keys[19]));
            for (int e = 0; e < cnt; ++e) {
                float xk = __uint_as_float(lbuf[e]);
                if (xk < tail) {                     // guard: skip stale keys
                    CHAIN_INSERT(keys, xk);
                    tail = fmaxf(fmaxf(keys[4], keys[9]), fmaxf(keys[14], keys[19]));
                }
            }
            cnt = 0;
            if (act) thr_l = fminf(thr_l, tail * 1.002f);
        };

        const int dbarr = set * 2;
        auto procbin = [&](int bin) {
            int j0 = g_offs[dbarr][bin];
            int j1 = g_offs[dbarr][bin + 1];
            for (int j = j0; j < j1; ++j) {
                float4 p = g_dbp[set][j];     // same addr all lanes: broadcast
                float dx = qpx - p.x, dy = qpy - p.y, dz = qpz - p.z;
                float d2 = fmaf(dx, dx, fmaf(dy, dy, dz * dz));
                if (d2 < thr_l) {
                    unsigned key = (__float_as_uint(d2) & 0xFFFFE000u)
                                 | (unsigned)__float_as_int(p.w);
                    if (cnt < LBUF) lbuf[cnt++] = key;
                    else { float xk = __uint_as_float(key); CHAIN_INSERT(keys, xk); }
                }
            }
        };

        auto laneneed = [&](int bin) -> bool {
            float loe = ZLO + (float)bin * BINW;
            float hie = loe + BINW;
            float dz = fmaxf(fmaxf(loe - qpz, qpz - hie), 0.f);
            return dz * dz < thr_l;          // thr_l=-1 for inactive -> false
        };

        int cb = zbin(qpz);
        int cbm = act ? cb : 0x7fffffff;
        int cbx = act ? cb : (int)0x80000000;
#pragma unroll
        for (int o = 16; o; o >>= 1) {
            cbm = min(cbm, __shfl_xor_sync(0xffffffffu, cbm, o));
            cbx = max(cbx, __shfl_xor_sync(0xffffffffu, cbx, o));
        }

        for (int bin = cbm; bin <= cbx; ++bin) {
            procbin(bin);
            if (__ballot_sync(0xffffffffu, cnt >= CTHRESH)) compact();
        }
        int dn = cbm - 1, up = cbx + 1;
        for (int it = 0; it < NBIN; ++it) {
            unsigned ndn = (dn >= 0)   ? __ballot_sync(0xffffffffu, laneneed(dn)) : 0u;
            unsigned nup = (up < NBIN) ? __ballot_sync(0xffffffffu, laneneed(up)) : 0u;
            if (!ndn && !nup) break;
            if (ndn) { procbin(dn); dn--; }
            if (nup) { procbin(up); up++; }
            if (__ballot_sync(0xffffffffu, cnt >= CTHRESH)) compact();
        }
        compact();

        // Exact epilogue over winners (skip sentinels: <20 found within cap).
        if (act) {
            const int qi = boff + iq;
            const float qz_own = xq[3 * qi + 2];
            float ell = fmaxf(0.015f * (qz_own - 10.0f), 0.15f);
            float inv_ls = 1.0f / (ell * ell);
            float hx = hq[3 * qi + 0], hy = hq[3 * qi + 1], hz = hq[3 * qi + 2];
            float nxr = nq[3 * qi + 0], nyr = nq[3 * qi + 1], nzr = nq[3 * qi + 2];
            float npx = fmaf(Rm[0], nxr, fmaf(Rm[3], nyr, Rm[6] * nzr));
            float npy = fmaf(Rm[1], nxr, fmaf(Rm[4], nyr, Rm[7] * nzr));
            float npz = fmaf(Rm[2], nxr, fmaf(Rm[5], nyr, Rm[8] * nzr));
            float rqv = rq[qi];
#pragma unroll
            for (int k = 0; k < KK; k++) {
                if (keys[k] < 1.0e30f) {
                    int idx = (int)(__float_as_uint(keys[k]) & 0x1FFFu);
                    int g3 = 3 * (boff + idx);
                    float dx = qpx - xdbr[g3 + 0];
                    float dy = qpy - xdbr[g3 + 1];
                    float dz = qpz - xdbr[g3 + 2];
                    float d2 = fmaf(dx, dx, fmaf(dy, dy, dz * dz));
                    float ndot = fmaf(npx, ndbr[g3 + 0],
                                      fmaf(npy, ndbr[g3 + 1], npz * ndbr[g3 + 2]));
                    float chx = hx - hdb[g3 + 0];
                    float chy = hy - hdb[g3 + 1];
                    float chz = hz - hdb[g3 + 2];
                    float cd = sqrtf(fmaf(chx, chx, fmaf(chy, chy, chz * chz)) + 1e-12f);
                    float rk = rdb[boff + idx];
                    float alpha = 0.2f / (0.1f + rqv + rk);
                    float nk = fmaxf(ndot * alpha, 0.0f);
                    sum += __expf(-(d2 * inv_ls + cd * 5.0f)) * nk;
                }
            }
        }
    }

    // Block reduce + single double atomic; last block finalizes.
#pragma unroll
    for (int o = 16; o > 0; o >>= 1) sum += __shfl_down_sync(0xffffffffu, sum, o);
    __shared__ float wsum[8];
    if (lane == 0) wsum[wid] = sum;
    __syncthreads();
    if (threadIdx.x == 0) {
        float bs = 0.f;
#pragma unroll
        for (int w2 = 0; w2 < 8; w2++) bs += wsum[w2];
        atomicAdd(&g_acc[s], (double)bs);
        __threadfence();
        unsigned done = atomicAdd(&g_done, 1u);
        if (done == (unsigned)(gridDim.x * gridDim.y) - 1u) {
            double s1 = (double)npts1[0] + (double)npts1[1];
            double s2 = (double)npts2[0] + (double)npts2[1];
            double k1 = g_acc[0] / (s1 * (double)KK);
            double k2 = g_acc[1] / (s2 * (double)KK);
            out[0] = (float)(0.5 * (k1 + k2));
        }
    }
}

extern "C" void kernel_launch(void* const* d_in, const int* in_sizes, int n_in,
                              void* d_out, int out_size) {
    const float* xyz1    = (const float*)d_in[0];
    const float* xyz2    = (const float*)d_in[1];
    const float* hsv1    = (const float*)d_in[2];
    const float* hsv2    = (const float*)d_in[3];
    const float* normal1 = (const float*)d_in[4];
    const float* normal2 = (const float*)d_in[5];
    const float* nres1   = (const float*)d_in[6];
    const float* nres2   = (const float*)d_in[7];
    const float* R12     = (const float*)d_in[8];
    const float* t12     = (const float*)d_in[9];
    const float* R21     = (const float*)d_in[10];
    const float* t21     = (const float*)d_in[11];
    const int*   npts1   = (const int*)d_in[12];
    const int*   npts2   = (const int*)d_in[13];
    float* out = (float*)d_out;

    init_kernel<<<2, 1024>>>();
    dim3 bgrid(BB * PP / 256, 2);
    hist_kernel<<<bgrid, 256>>>(xyz1, xyz2, R12, t12, R21, t21, npts1, npts2);
    scan_kernel<<<1, NBIN>>>();
    scatter_kernel<<<bgrid, 256>>>(xyz1, xyz2, R12, t12, R21, t21, npts1, npts2);
    dim3 qgrid(32, 4);
    query_kernel<<<qgrid, 256>>>(xyz1, hsv1, normal1, nres1,
                                 xyz2, hsv2, normal2, nres2,
                                 R12, t12, R21, t21, npts1, npts2, out);
}

// round 12
// speedup vs baseline: 8.3528x; 1.3639x over previous
#include <cuda_runtime.h>
#include <math.h>

#define BB 2
#define PP 8192
#define KK 20
#define NBIN 128
#define ZLO 1.0f
#define ZSPAN 60.0f
#define INVBINW (NBIN / ZSPAN)
#define BINW (ZSPAN / NBIN)
#define DCAP2 9.0f      // 3 m search-radius cap (dropped terms < 4e-7 each)
#define LBUF 48
#define CTHRESH 32

__device__ double g_acc[2];
__device__ unsigned g_done;
__device__ int g_hist[8][NBIN];        // [set*2 + (0=db,1=query)]
__device__ int g_offs[8][NBIN + 1];
__device__ int g_curs[8][NBIN];
__device__ float4 g_dbp[4][PP];        // z-binned db points (x,y,z, idx bits)
__device__ float4 g_qp[4][PP];         // z-binned transformed queries

// Insert packed key x into 4 sorted chains of 5 (tails at 4,9,14,19).
#define CHAIN_INSERT(keys, x)                                                   \
    do {                                                                        \
        float tt0 = keys[4], tt1 = keys[9], tt2 = keys[14], tt3 = keys[19];     \
        int sel_ = 0; float bv_ = tt0;                                          \
        if (tt1 > bv_) { bv_ = tt1; sel_ = 1; }                                 \
        if (tt2 > bv_) { bv_ = tt2; sel_ = 2; }                                 \
        if (tt3 > bv_) { bv_ = tt3; sel_ = 3; }                                 \
        float x0_ = (sel_ == 0) ? (x) : 3.3e38f;                                \
        float x1_ = (sel_ == 1) ? (x) : 3.3e38f;                                \
        float x2_ = (sel_ == 2) ? (x) : 3.3e38f;                                \
        float x3_ = (sel_ == 3) ? (x) : 3.3e38f;                                \
        _Pragma("unroll")                                                       \
        for (int k_ = 0; k_ < 5; k_++) {                                        \
            float lo_ = fminf(x0_, keys[k_]); x0_ = fmaxf(x0_, keys[k_]); keys[k_] = lo_; } \
        _Pragma("unroll")                                                       \
        for (int k_ = 5; k_ < 10; k_++) {                                       \
            float lo_ = fminf(x1_, keys[k_]); x1_ = fmaxf(x1_, keys[k_]); keys[k_] = lo_; } \
        _Pragma("unroll")                                                       \
        for (int k_ = 10; k_ < 15; k_++) {                                      \
            float lo_ = fminf(x2_, keys[k_]); x2_ = fmaxf(x2_, keys[k_]); keys[k_] = lo_; } \
        _Pragma("unroll")                                                       \
        for (int k_ = 15; k_ < 20; k_++) {                                      \
            float lo_ = fminf(x3_, keys[k_]); x3_ = fmaxf(x3_, keys[k_]); keys[k_] = lo_; } \
    } while (0)

__device__ __forceinline__ int zbin(float z) {
    return min(NBIN - 1, max(0, (int)floorf((z - ZLO) * INVBINW)));
}

__global__ void init_kernel() {
    int i = blockIdx.x * blockDim.x + threadIdx.x;
    if (i == 0) { g_acc[0] = 0.0; g_acc[1] = 0.0; g_done = 0u; }
    if (i < 8 * NBIN) ((int*)g_hist)[i] = 0;
}

__global__ void hist_kernel(const float* __restrict__ xyz1, const float* __restrict__ xyz2,
                            const float* __restrict__ R12, const float* __restrict__ t12,
                            const float* __restrict__ R21, const float* __restrict__ t21,
                            const int* __restrict__ npts1, const int* __restrict__ npts2) {
    const int s = blockIdx.y;
    const int gi = blockIdx.x * blockDim.x + threadIdx.x;
    const int b = gi >> 13;
    const int i = gi & (PP - 1);
    const int set = s * BB + b;
    const float* dbsrc = s ? xyz1 : xyz2;
    const int ldb = (s ? npts1 : npts2)[b];
    if (i < ldb)
        atomicAdd(&g_hist[set * 2][zbin(dbsrc[3 * gi + 2])], 1);
    const float* qsrc = s ? xyz2 : xyz1;
    const int lq = (s ? npts2 : npts1)[b];
    if (i < lq) {
        const float* Rm = (s ? R21 : R12) + b * 9;
        const float* tv = (s ? t21 : t12) + b * 3;
        float ux = qsrc[3 * gi + 0] - tv[0];
        float uy = qsrc[3 * gi + 1] - tv[1];
        float uz = qsrc[3 * gi + 2] - tv[2];
        float qpz = fmaf(Rm[2], ux, fmaf(Rm[5], uy, Rm[8] * uz));
        atomicAdd(&g_hist[set * 2 + 1][zbin(qpz)], 1);
    }
}

// Parallel scan: one block per histogram array (8 blocks).
__global__ void scan_kernel() {
    __shared__ int sv[NBIN];
    const int a = blockIdx.x;
    const int t = threadIdx.x;
    int v = g_hist[a][t];
    sv[t] = v;
    __syncthreads();
    for (int o = 1; o < NBIN; o <<= 1) {
        int x = (t >= o) ? sv[t - o] : 0;
        __syncthreads();
        sv[t] += x;
        __syncthreads();
    }
    g_offs[a][t + 1] = sv[t];
    g_curs[a][t] = sv[t] - v;
    if (t == 0) g_offs[a][0] = 0;
}

__global__ void scatter_kernel(const float* __restrict__ xyz1, const float* __restrict__ xyz2,
                               const float* __restrict__ R12, const float* __restrict__ t12,
                               const float* __restrict__ R21, const float* __restrict__ t21,
                               const int* __restrict__ npts1, const int* __restrict__ npts2) {
    const int s = blockIdx.y;
    const int gi = blockIdx.x * blockDim.x + threadIdx.x;
    const int b = gi >> 13;
    const int i = gi & (PP - 1);
    const int set = s * BB + b;
    const float* dbsrc = s ? xyz1 : xyz2;
    const int ldb = (s ? npts1 : npts2)[b];
    if (i < ldb) {
        float x = dbsrc[3 * gi + 0], y = dbsrc[3 * gi + 1], z = dbsrc[3 * gi + 2];
        int pos = atomicAdd(&g_curs[set * 2][zbin(z)], 1);
        g_dbp[set][pos] = make_float4(x, y, z, __int_as_float(i));
    }
    const float* qsrc = s ? xyz2 : xyz1;
    const int lq = (s ? npts2 : npts1)[b];
    if (i < lq) {
        const float* Rm = (s ? R21 : R12) + b * 9;
        const float* tv = (s ? t21 : t12) + b * 3;
        float ux = qsrc[3 * gi + 0] - tv[0];
        float uy = qsrc[3 * gi + 1] - tv[1];
        float uz = qsrc[3 * gi + 2] - tv[2];
        float qpx = fmaf(Rm[0], ux, fmaf(Rm[3], uy, Rm[6] * uz));
        float qpy = fmaf(Rm[1], ux, fmaf(Rm[4], uy, Rm[7] * uz));
        float qpz = fmaf(Rm[2], ux, fmaf(Rm[5], uy, Rm[8] * uz));
        int pos = atomicAdd(&g_curs[set * 2 + 1][zbin(qpz)], 1);
        g_qp[set][pos] = make_float4(qpx, qpy, qpz, __int_as_float(i));
    }
}

// Warp pair shares 32 z-sorted queries: even warp walks bins mid->0, odd warp
// mid+1->NBIN-1. Chunk-4 point processing (MLP=4). Odd publishes top-20; even
// merges (guarded) and runs the exact epilogue.
__global__ __launch_bounds__(256) void query_kernel(
    const float* __restrict__ xyz1, const float* __restrict__ hsv1,
    const float* __restrict__ normal1, const float* __restrict__ nres1,
    const float* __restrict__ xyz2, const float* __restrict__ hsv2,
    const float* __restrict__ normal2, const float* __restrict__ nres2,
    const float* __restrict__ R12, const float* __restrict__ t12,
    const float* __restrict__ R21, const float* __restrict__ t21,
    const int* __restrict__ npts1, const int* __restrict__ npts2,
    float* __restrict__ out)
{
    const int set = blockIdx.y;
    const int s = set >> 1, b = set & 1;
    const int lane = threadIdx.x & 31;
    const int wid = threadIdx.x >> 5;
    const int wpair = wid >> 1;
    const int dirn = wid & 1;              // 0 = down (incl. lower center), 1 = up
    const int boff = b * PP;

    const float* xq   = s ? xyz2 : xyz1;
    const float* hq   = s ? hsv2 : hsv1;
    const float* nq   = s ? normal2 : normal1;
    const float* rq   = s ? nres2 : nres1;
    const float* xdbr = s ? xyz1 : xyz2;
    const float* ndbr = s ? normal1 : normal2;
    const float* hdb  = s ? hsv1 : hsv2;
    const float* rdb  = s ? nres1 : nres2;
    const float* Rm   = (s ? R21 : R12) + b * 9;
    const int lq = (s ? npts2 : npts1)[b];

    const int base = (blockIdx.x * 4 + wpair) * 32;
    const int pos = base + lane;
    const bool act = (base < lq) && (pos < lq);

    float4 qr = (base < lq) ? g_qp[set][act ? pos : base]
                            : make_float4(0.f, 0.f, 0.f, __int_as_float(0));
    const float qpx = qr.x, qpy = qr.y, qpz = qr.z;
    const int iq = __float_as_int(qr.w);

    float keys[KK];
#pragma unroll
    for (int k = 0; k < KK; k++) keys[k] = 3.0e38f;
    float sum = 0.f;

    __shared__ float skeys[4][32][KK + 1];

    if (base < lq) {
        float thr_l = act ? DCAP2 : -1.0f;
        int cnt = 0;
        unsigned lbuf[LBUF];

        auto compact = [&]() {
            float tail = fmaxf(fmaxf(keys[4], keys[9]), fmaxf(keys[14], keys[19]));
            for (int e = 0; e < cnt; ++e) {
                float xk = __uint_as_float(lbuf[e]);
                if (xk < tail) {
                    CHAIN_INSERT(keys, xk);
                    tail = fmaxf(fmaxf(keys[4], keys[9]), fmaxf(keys[14], keys[19]));
                }
            }
            cnt = 0;
            if (act) thr_l = fminf(thr_l, tail * 1.002f);
        };

        const int dbarr = set * 2;
        const float4* __restrict__ dbp = g_dbp[set];

        auto accept = [&](float d2, int j) {
            unsigned key = (__float_as_uint(d2) & 0xFFFFE000u)
                         | (unsigned)__float_as_int(dbp[j].w);
            if (cnt < LBUF) lbuf[cnt++] = key;
            else { float xk = __uint_as_float(key); CHAIN_INSERT(keys, xk); }
        };

        auto procbin = [&](int bin) {
            const int j0 = g_offs[dbarr][bin];
            const int j1 = g_offs[dbarr][bin + 1];
            int j = j0;
            for (; j + 4 <= j1; j += 4) {
                float4 p0 = dbp[j + 0];
                float4 p1 = dbp[j + 1];
                float4 p2 = dbp[j + 2];
                float4 p3 = dbp[j + 3];
                float dx0 = qpx - p0.x, dy0 = qpy - p0.y, dz0 = qpz - p0.z;
                float dx1 = qpx - p1.x, dy1 = qpy - p1.y, dz1 = qpz - p1.z;
                float dx2 = qpx - p2.x, dy2 = qpy - p2.y, dz2 = qpz - p2.z;
                float dx3 = qpx - p3.x, dy3 = qpy - p3.y, dz3 = qpz - p3.z;
                float d0 = fmaf(dx0, dx0, fmaf(dy0, dy0, dz0 * dz0));
                float d1 = fmaf(dx1, dx1, fmaf(dy1, dy1, dz1 * dz1));
                float d2v = fmaf(dx2, dx2, fmaf(dy2, dy2, dz2 * dz2));
                float d3 = fmaf(dx3, dx3, fmaf(dy3, dy3, dz3 * dz3));
                float m4 = fminf(fminf(d0, d1), fminf(d2v, d3));
                if (m4 < thr_l) {
                    if (d0 < thr_l) accept(d0, j + 0);
                    if (d1 < thr_l) accept(d1, j + 1);
                    if (d2v < thr_l) accept(d2v, j + 2);
                    if (d3 < thr_l) accept(d3, j + 3);
                }
            }
            for (; j < j1; ++j) {
                float4 p = dbp[j];
                float dx = qpx - p.x, dy = qpy - p.y, dz = qpz - p.z;
                float d2 = fmaf(dx, dx, fmaf(dy, dy, dz * dz));
                if (d2 < thr_l) accept(d2, j);
            }
        };

        auto laneneed = [&](int bin) -> bool {
            float loe = ZLO + (float)bin * BINW;
            float hie = loe + BINW;
            float dz = fmaxf(fmaxf(loe - qpz, qpz - hie), 0.f);
            return dz * dz < thr_l;          // false for inactive (thr_l = -1)
        };

        int cb = zbin(qpz);
        int cbm = act ? cb : 0x7fffffff;
        int cbx = act ? cb : (int)0x80000000;
#pragma unroll
        for (int o = 16; o; o >>= 1) {
            cbm = min(cbm, __shfl_xor_sync(0xffffffffu, cbm, o));
            cbx = max(cbx, __shfl_xor_sync(0xffffffffu, cbx, o));
        }
        const int mid = (cbm + cbx) >> 1;

        int bin = dirn ? (mid + 1) : mid;
        const int step = dirn ? 1 : -1;
        while (bin >= 0 && bin < NBIN) {
            if (!__ballot_sync(0xffffffffu, laneneed(bin))) break;
            procbin(bin);
            if (__ballot_sync(0xffffffffu, cnt >= CTHRESH)) compact();
            bin += step;
        }
        compact();
    }

    // Pair merge: odd warp publishes; even warp folds (guarded).
    if (dirn == 1) {
#pragma unroll
        for (int k = 0; k < KK; k++) skeys[wpair][lane][k] = keys[k];
    }
    __syncthreads();

    if (dirn == 0) {
        float tail = fmaxf(fmaxf(keys[4], keys[9]), fmaxf(keys[14], keys[19]));
#pragma unroll
        for (int k = 0; k < KK; k++) {
            float x = skeys[wpair][lane][k];
            if (x < tail) {
                CHAIN_INSERT(keys, x);
                tail = fmaxf(fmaxf(keys[4], keys[9]), fmaxf(keys[14], keys[19]));
            }
        }

        // Exact epilogue over merged winners (skip sentinels).
        if (act) {
            const int qi = boff + iq;
            const float qz_own = xq[3 * qi + 2];
            float ell = fmaxf(0.015f * (qz_own - 10.0f), 0.15f);
            float inv_ls = 1.0f / (ell * ell);
            float hx = hq[3 * qi + 0], hy = hq[3 * qi + 1], hz = hq[3 * qi + 2];
            float nxr = nq[3 * qi + 0], nyr = nq[3 * qi + 1], nzr = nq[3 * qi + 2];
            float npx = fmaf(Rm[0], nxr, fmaf(Rm[3], nyr, Rm[6] * nzr));
            float npy = fmaf(Rm[1], nxr, fmaf(Rm[4], nyr, Rm[7] * nzr));
            float npz = fmaf(Rm[2], nxr, fmaf(Rm[5], nyr, Rm[8] * nzr));
            float rqv = rq[qi];
#pragma unroll
            for (int k = 0; k < KK; k++) {
                if (keys[k] < 1.0e30f) {
                    int idx = (int)(__float_as_uint(keys[k]) & 0x1FFFu);
                    int g3 = 3 * (boff + idx);
                    float dx = qpx - xdbr[g3 + 0];
                    float dy = qpy - xdbr[g3 + 1];
                    float dz = qpz - xdbr[g3 + 2];
                    float d2 = fmaf(dx, dx, fmaf(dy, dy, dz * dz));
                    float ndot = fmaf(npx, ndbr[g3 + 0],
                                      fmaf(npy, ndbr[g3 + 1], npz * ndbr[g3 + 2]));
                    float chx = hx - hdb[g3 + 0];
                    float chy = hy - hdb[g3 + 1];
                    float chz = hz - hdb[g3 + 2];
                    float cd = sqrtf(fmaf(chx, chx, fmaf(chy, chy, chz * chz)) + 1e-12f);
                    float rk = rdb[boff + idx];
                    float alpha = 0.2f / (0.1f + rqv + rk);
                    float nk = fmaxf(ndot * alpha, 0.0f);
                    sum += __expf(-(d2 * inv_ls + cd * 5.0f)) * nk;
                }
            }
        }
    }

    // Block reduce + single double atomic; last block finalizes.
#pragma unroll
    for (int o = 16; o > 0; o >>= 1) sum += __shfl_down_sync(0xffffffffu, sum, o);
    __shared__ float wsum[8];
    if (lane == 0) wsum[wid] = sum;
    __syncthreads();
    if (threadIdx.x == 0) {
        float bs = 0.f;
#pragma unroll
        for (int w2 = 0; w2 < 8; w2++) bs += wsum[w2];
        atomicAdd(&g_acc[s], (double)bs);
        __threadfence();
        unsigned done = atomicAdd(&g_done, 1u);
        if (done == (unsigned)(gridDim.x * gridDim.y) - 1u) {
            double s1 = (double)npts1[0] + (double)npts1[1];
            double s2 = (double)npts2[0] + (double)npts2[1];
            double k1 = g_acc[0] / (s1 * (double)KK);
            double k2 = g_acc[1] / (s2 * (double)KK);
            out[0] = (float)(0.5 * (k1 + k2));
        }
    }
}

extern "C" void kernel_launch(void* const* d_in, const int* in_sizes, int n_in,
                              void* d_out, int out_size) {
    const float* xyz1    = (const float*)d_in[0];
    const float* xyz2    = (const float*)d_in[1];
    const float* hsv1    = (const float*)d_in[2];
    const float* hsv2    = (const float*)d_in[3];
    const float* normal1 = (const float*)d_in[4];
    const float* normal2 = (const float*)d_in[5];
    const float* nres1   = (const float*)d_in[6];
    const float* nres2   = (const float*)d_in[7];
    const float* R12     = (const float*)d_in[8];
    const float* t12     = (const float*)d_in[9];
    const float* R21     = (const float*)d_in[10];
    const float* t21     = (const float*)d_in[11];
    const int*   npts1   = (const int*)d_in[12];
    const int*   npts2   = (const int*)d_in[13];
    float* out = (float*)d_out;

    init_kernel<<<2, 1024>>>();
    dim3 bgrid(BB * PP / 256, 2);
    hist_kernel<<<bgrid, 256>>>(xyz1, xyz2, R12, t12, R21, t21, npts1, npts2);
    scan_kernel<<<8, NBIN>>>();
    scatter_kernel<<<bgrid, 256>>>(xyz1, xyz2, R12, t12, R21, t21, npts1, npts2);
    dim3 qgrid(BB * PP / 128, 4);
    query_kernel<<<qgrid, 256>>>(xyz1, hsv1, normal1, nres1,
                                 xyz2, hsv2, normal2, nres2,
                                 R12, t12, R21, t21, npts1, npts2, out);
}

// round 13
// speedup vs baseline: 13.1002x; 1.5684x over previous
#include <cuda_runtime.h>
#include <math.h>

#define BB 2
#define PP 8192
#define KK 20
#define NBIN 128
#define ZLO 1.0f
#define ZSPAN 60.0f
#define INVBINW (NBIN / ZSPAN)
#define BINW (ZSPAN / NBIN)
#define DCAP2 9.0f      // 3 m search-radius cap (dropped terms < 4e-7 each)
#define LBUF 48
#define CTHRESH 32

__device__ double g_acc[2];            // zero at load; self-cleaned by query_kernel
__device__ unsigned g_done;
__device__ int g_hist[8][NBIN];        // zero at load; self-cleaned by scan_kernel
__device__ int g_offs[8][NBIN + 1];
__device__ int g_curs[8][NBIN];
__device__ float4 g_dbp[4][PP];        // z-binned db points (x,y,z, idx bits)
__device__ float4 g_qp[4][PP];         // z-binned transformed queries

// Insert packed key x into 4 sorted chains of 5 (tails at 4,9,14,19).
#define CHAIN_INSERT(keys, x)                                                   \
    do {                                                                        \
        float tt0 = keys[4], tt1 = keys[9], tt2 = keys[14], tt3 = keys[19];     \
        int sel_ = 0; float bv_ = tt0;                                          \
        if (tt1 > bv_) { bv_ = tt1; sel_ = 1; }                                 \
        if (tt2 > bv_) { bv_ = tt2; sel_ = 2; }                                 \
        if (tt3 > bv_) { bv_ = tt3; sel_ = 3; }                                 \
        float x0_ = (sel_ == 0) ? (x) : 3.3e38f;                                \
        float x1_ = (sel_ == 1) ? (x) : 3.3e38f;                                \
        float x2_ = (sel_ == 2) ? (x) : 3.3e38f;                                \
        float x3_ = (sel_ == 3) ? (x) : 3.3e38f;                                \
        _Pragma("unroll")                                                       \
        for (int k_ = 0; k_ < 5; k_++) {                                        \
            float lo_ = fminf(x0_, keys[k_]); x0_ = fmaxf(x0_, keys[k_]); keys[k_] = lo_; } \
        _Pragma("unroll")                                                       \
        for (int k_ = 5; k_ < 10; k_++) {                                       \
            float lo_ = fminf(x1_, keys[k_]); x1_ = fmaxf(x1_, keys[k_]); keys[k_] = lo_; } \
        _Pragma("unroll")                                                       \
        for (int k_ = 10; k_ < 15; k_++) {                                      \
            float lo_ = fminf(x2_, keys[k_]); x2_ = fmaxf(x2_, keys[k_]); keys[k_] = lo_; } \
        _Pragma("unroll")                                                       \
        for (int k_ = 15; k_ < 20; k_++) {                                      \
            float lo_ = fminf(x3_, keys[k_]); x3_ = fmaxf(x3_, keys[k_]); keys[k_] = lo_; } \
    } while (0)

__device__ __forceinline__ int zbin(float z) {
    return min(NBIN - 1, max(0, (int)floorf((z - ZLO) * INVBINW)));
}

__global__ void hist_kernel(const float* __restrict__ xyz1, const float* __restrict__ xyz2,
                            const float* __restrict__ R12, const float* __restrict__ t12,
                            const float* __restrict__ R21, const float* __restrict__ t21,
                            const int* __restrict__ npts1, const int* __restrict__ npts2) {
    const int s = blockIdx.y;
    const int gi = blockIdx.x * blockDim.x + threadIdx.x;
    const int b = gi >> 13;
    const int i = gi & (PP - 1);
    const int set = s * BB + b;
    const float* dbsrc = s ? xyz1 : xyz2;
    const int ldb = (s ? npts1 : npts2)[b];
    if (i < ldb)
        atomicAdd(&g_hist[set * 2][zbin(dbsrc[3 * gi + 2])], 1);
    const float* qsrc = s ? xyz2 : xyz1;
    const int lq = (s ? npts2 : npts1)[b];
    if (i < lq) {
        const float* Rm = (s ? R21 : R12) + b * 9;
        const float* tv = (s ? t21 : t12) + b * 3;
        float ux = qsrc[3 * gi + 0] - tv[0];
        float uy = qsrc[3 * gi + 1] - tv[1];
        float uz = qsrc[3 * gi + 2] - tv[2];
        float qpz = fmaf(Rm[2], ux, fmaf(Rm[5], uy, Rm[8] * uz));
        atomicAdd(&g_hist[set * 2 + 1][zbin(qpz)], 1);
    }
}

// Parallel scan: one block per histogram array; zeroes g_hist after reading
// (self-cleaning: next run starts from zeroed histograms).
__global__ void scan_kernel() {
    __shared__ int sv[NBIN];
    const int a = blockIdx.x;
    const int t = threadIdx.x;
    int v = g_hist[a][t];
    g_hist[a][t] = 0;
    sv[t] = v;
    __syncthreads();
    for (int o = 1; o < NBIN; o <<= 1) {
        int x = (t >= o) ? sv[t - o] : 0;
        __syncthreads();
        sv[t] += x;
        __syncthreads();
    }
    g_offs[a][t + 1] = sv[t];
    g_curs[a][t] = sv[t] - v;
    if (t == 0) g_offs[a][0] = 0;
}

__global__ void scatter_kernel(const float* __restrict__ xyz1, const float* __restrict__ xyz2,
                               const float* __restrict__ R12, const float* __restrict__ t12,
                               const float* __restrict__ R21, const float* __restrict__ t21,
                               const int* __restrict__ npts1, const int* __restrict__ npts2) {
    const int s = blockIdx.y;
    const int gi = blockIdx.x * blockDim.x + threadIdx.x;
    const int b = gi >> 13;
    const int i = gi & (PP - 1);
    const int set = s * BB + b;
    const float* dbsrc = s ? xyz1 : xyz2;
    const int ldb = (s ? npts1 : npts2)[b];
    if (i < ldb) {
        float x = dbsrc[3 * gi + 0], y = dbsrc[3 * gi + 1], z = dbsrc[3 * gi + 2];
        int pos = atomicAdd(&g_curs[set * 2][zbin(z)], 1);
        g_dbp[set][pos] = make_float4(x, y, z, __int_as_float(i));
    }
    const float* qsrc = s ? xyz2 : xyz1;
    const int lq = (s ? npts2 : npts1)[b];
    if (i < lq) {
        const float* Rm = (s ? R21 : R12) + b * 9;
        const float* tv = (s ? t21 : t12) + b * 3;
        float ux = qsrc[3 * gi + 0] - tv[0];
        float uy = qsrc[3 * gi + 1] - tv[1];
        float uz = qsrc[3 * gi + 2] - tv[2];
        float qpx = fmaf(Rm[0], ux, fmaf(Rm[3], uy, Rm[6] * uz));
        float qpy = fmaf(Rm[1], ux, fmaf(Rm[4], uy, Rm[7] * uz));
        float qpz = fmaf(Rm[2], ux, fmaf(Rm[5], uy, Rm[8] * uz));
        int pos = atomicAdd(&g_curs[set * 2 + 1][zbin(qpz)], 1);
        g_qp[set][pos] = make_float4(qpx, qpy, qpz, __int_as_float(i));
    }
}

// 4 warps share 32 z-sorted queries; stride-2 bin walks:
//   sub0: mid, mid-2, ...   sub1: mid-1, mid-3, ...
//   sub2: mid+1, mid+3, ... sub3: mid+2, mid+4, ...
// Monotone sequences keep the ballot stop conservative. Subs 1-3 publish
// top-20s; sub0 merges (guarded) and runs the exact epilogue.
__global__ __launch_bounds__(256) void query_kernel(
    const float* __restrict__ xyz1, const float* __restrict__ hsv1,
    const float* __restrict__ normal1, const float* __restrict__ nres1,
    const float* __restrict__ xyz2, const float* __restrict__ hsv2,
    const float* __restrict__ normal2, const float* __restrict__ nres2,
    const float* __restrict__ R12, const float* __restrict__ t12,
    const float* __restrict__ R21, const float* __restrict__ t21,
    const int* __restrict__ npts1, const int* __restrict__ npts2,
    float* __restrict__ out)
{
    const int set = blockIdx.y;
    const int s = set >> 1, b = set & 1;
    const int lane = threadIdx.x & 31;
    const int wid = threadIdx.x >> 5;
    const int wgrp = wid >> 2;             // 2 query groups per block
    const int sub = wid & 3;               // 4 walk shards per group
    const int boff = b * PP;

    const float* xq   = s ? xyz2 : xyz1;
    const float* hq   = s ? hsv2 : hsv1;
    const float* nq   = s ? normal2 : normal1;
    const float* rq   = s ? nres2 : nres1;
    const float* xdbr = s ? xyz1 : xyz2;
    const float* ndbr = s ? normal1 : normal2;
    const float* hdb  = s ? hsv1 : hsv2;
    const float* rdb  = s ? nres1 : nres2;
    const float* Rm   = (s ? R21 : R12) + b * 9;
    const int lq = (s ? npts2 : npts1)[b];

    const int base = (blockIdx.x * 2 + wgrp) * 32;
    const int pos = base + lane;
    const bool act = (base < lq) && (pos < lq);

    float4 qr = (base < lq) ? g_qp[set][act ? pos : base]
                            : make_float4(0.f, 0.f, 0.f, __int_as_float(0));
    const float qpx = qr.x, qpy = qr.y, qpz = qr.z;
    const int iq = __float_as_int(qr.w);

    float keys[KK];
#pragma unroll
    for (int k = 0; k < KK; k++) keys[k] = 3.0e38f;
    float sum = 0.f;

    __shared__ float skeys[2][3][32][KK + 1];

    if (base < lq) {
        float thr_l = act ? DCAP2 : -1.0f;
        int cnt = 0;
        unsigned lbuf[LBUF];

        auto compact = [&]() {
            float tail = fmaxf(fmaxf(keys[4], keys[9]), fmaxf(keys[14], keys[19]));
            for (int e = 0; e < cnt; ++e) {
                float xk = __uint_as_float(lbuf[e]);
                if (xk < tail) {
                    CHAIN_INSERT(keys, xk);
                    tail = fmaxf(fmaxf(keys[4], keys[9]), fmaxf(keys[14], keys[19]));
                }
            }
            cnt = 0;
            if (act) thr_l = fminf(thr_l, tail * 1.002f);
        };

        const int dbarr = set * 2;
        const float4* __restrict__ dbp = g_dbp[set];

        auto accept = [&](float d2, int j) {
            unsigned key = (__float_as_uint(d2) & 0xFFFFE000u)
                         | (unsigned)__float_as_int(dbp[j].w);
            if (cnt < LBUF) lbuf[cnt++] = key;
            else { float xk = __uint_as_float(key); CHAIN_INSERT(keys, xk); }
        };

        auto procbin = [&](int bin) {
            const int j0 = g_offs[dbarr][bin];
            const int j1 = g_offs[dbarr][bin + 1];
            int j = j0;
            for (; j + 4 <= j1; j += 4) {
                float4 p0 = dbp[j + 0];
                float4 p1 = dbp[j + 1];
                float4 p2 = dbp[j + 2];
                float4 p3 = dbp[j + 3];
                float dx0 = qpx - p0.x, dy0 = qpy - p0.y, dz0 = qpz - p0.z;
                float dx1 = qpx - p1.x, dy1 = qpy - p1.y, dz1 = qpz - p1.z;
                float dx2 = qpx - p2.x, dy2 = qpy - p2.y, dz2 = qpz - p2.z;
                float dx3 = qpx - p3.x, dy3 = qpy - p3.y, dz3 = qpz - p3.z;
                float d0 = fmaf(dx0, dx0, fmaf(dy0, dy0, dz0 * dz0));
                float d1 = fmaf(dx1, dx1, fmaf(dy1, dy1, dz1 * dz1));
                float d2v = fmaf(dx2, dx2, fmaf(dy2, dy2, dz2 * dz2));
                float d3 = fmaf(dx3, dx3, fmaf(dy3, dy3, dz3 * dz3));
                float m4 = fminf(fminf(d0, d1), fminf(d2v, d3));
                if (m4 < thr_l) {
                    if (d0 < thr_l) accept(d0, j + 0);
                    if (d1 < thr_l) accept(d1, j + 1);
                    if (d2v < thr_l) accept(d2v, j + 2);
                    if (d3 < thr_l) accept(d3, j + 3);
                }
            }
            for (; j < j1; ++j) {
                float4 p = dbp[j];
                float dx = qpx - p.x, dy = qpy - p.y, dz = qpz - p.z;
                float d2 = fmaf(dx, dx, fmaf(dy, dy, dz * dz));
                if (d2 < thr_l) accept(d2, j);
            }
        };

        auto laneneed = [&](int bin) -> bool {
            float loe = ZLO + (float)bin * BINW;
            float hie = loe + BINW;
            float dz = fmaxf(fmaxf(loe - qpz, qpz - hie), 0.f);
            return dz * dz < thr_l;          // false for inactive (thr_l = -1)
        };

        int cb = zbin(qpz);
        int cbm = act ? cb : 0x7fffffff;
        int cbx = act ? cb : (int)0x80000000;
#pragma unroll
        for (int o = 16; o; o >>= 1) {
            cbm = min(cbm, __shfl_xor_sync(0xffffffffu, cbm, o));
            cbx = max(cbx, __shfl_xor_sync(0xffffffffu, cbx, o));
        }
        const int mid = (cbm + cbx) >> 1;

        // Stride-2 walk per sub-warp (monotone in z-distance).
        int bin  = (sub == 0) ? mid     : (sub == 1) ? mid - 1
                 : (sub == 2) ? mid + 1 : mid + 2;
        const int step = (sub < 2) ? -2 : 2;
        while (bin >= 0 && bin < NBIN) {
            if (!__ballot_sync(0xffffffffu, laneneed(bin))) break;
            procbin(bin);
            if (__ballot_sync(0xffffffffu, cnt >= CTHRESH)) compact();
            bin += step;
        }
        compact();
    }

    // Shard merge: subs 1-3 publish; sub 0 folds (guarded).
    if (sub > 0) {
#pragma unroll
        for (int k = 0; k < KK; k++) skeys[wgrp][sub - 1][lane][k] = keys[k];
    }
    __syncthreads();

    if (sub == 0) {
        float tail = fmaxf(fmaxf(keys[4], keys[9]), fmaxf(keys[14], keys[19]));
#pragma unroll
        for (int ws = 0; ws < 3; ws++) {
#pragma unroll
            for (int k = 0; k < KK; k++) {
                float x = skeys[wgrp][ws][lane][k];
                if (x < tail) {
                    CHAIN_INSERT(keys, x);
                    tail = fmaxf(fmaxf(keys[4], keys[9]), fmaxf(keys[14], keys[19]));
                }
            }
        }

        // Exact epilogue over merged winners (skip sentinels).
        if (act) {
            const int qi = boff + iq;
            const float qz_own = xq[3 * qi + 2];
            float ell = fmaxf(0.015f * (qz_own - 10.0f), 0.15f);
            float inv_ls = 1.0f / (ell * ell);
            float hx = hq[3 * qi + 0], hy = hq[3 * qi + 1], hz = hq[3 * qi + 2];
            float nxr = nq[3 * qi + 0], nyr = nq[3 * qi + 1], nzr = nq[3 * qi + 2];
            float npx = fmaf(Rm[0], nxr, fmaf(Rm[3], nyr, Rm[6] * nzr));
            float npy = fmaf(Rm[1], nxr, fmaf(Rm[4], nyr, Rm[7] * nzr));
            float npz = fmaf(Rm[2], nxr, fmaf(Rm[5], nyr, Rm[8] * nzr));
            float rqv = rq[qi];
#pragma unroll
            for (int k = 0; k < KK; k++) {
                if (keys[k] < 1.0e30f) {
                    int idx = (int)(__float_as_uint(keys[k]) & 0x1FFFu);
                    int g3 = 3 * (boff + idx);
                    float dx = qpx - xdbr[g3 + 0];
                    float dy = qpy - xdbr[g3 + 1];
                    float dz = qpz - xdbr[g3 + 2];
                    float d2 = fmaf(dx, dx, fmaf(dy, dy, dz * dz));
                    float ndot = fmaf(npx, ndbr[g3 + 0],
                                      fmaf(npy, ndbr[g3 + 1], npz * ndbr[g3 + 2]));
                    float chx = hx - hdb[g3 + 0];
                    float chy = hy - hdb[g3 + 1];
                    float chz = hz - hdb[g3 + 2];
                    float cd = sqrtf(fmaf(chx, chx, fmaf(chy, chy, chz * chz)) + 1e-12f);
                    float rk = rdb[boff + idx];
                    float alpha = 0.2f / (0.1f + rqv + rk);
                    float nk = fmaxf(ndot * alpha, 0.0f);
                    sum += __expf(-(d2 * inv_ls + cd * 5.0f)) * nk;
                }
            }
        }
    }

    // Block reduce + single double atomic; last block finalizes and
    // self-cleans accumulator state for the next graph replay.
#pragma unroll
    for (int o = 16; o > 0; o >>= 1) sum += __shfl_down_sync(0xffffffffu, sum, o);
    __shared__ float wsum[8];
    if (lane == 0) wsum[wid] = sum;
    __syncthreads();
    if (threadIdx.x == 0) {
        float bs = 0.f;
#pragma unroll
        for (int w2 = 0; w2 < 8; w2++) bs += wsum[w2];
        atomicAdd(&g_acc[s], (double)bs);
        __threadfence();
        unsigned done = atomicAdd(&g_done, 1u);
        if (done == (unsigned)(gridDim.x * gridDim.y) - 1u) {
            double s1 = (double)npts1[0] + (double)npts1[1];
            double s2 = (double)npts2[0] + (double)npts2[1];
            double k1 = g_acc[0] / (s1 * (double)KK);
            double k2 = g_acc[1] / (s2 * (double)KK);
            out[0] = (float)(0.5 * (k1 + k2));
            g_acc[0] = 0.0;        // self-clean for next replay
            g_acc[1] = 0.0;
            g_done = 0u;
        }
    }
}

extern "C" void kernel_launch(void* const* d_in, const int* in_sizes, int n_in,
                              void* d_out, int out_size) {
    const float* xyz1    = (const float*)d_in[0];
    const float* xyz2    = (const float*)d_in[1];
    const float* hsv1    = (const float*)d_in[2];
    const float* hsv2    = (const float*)d_in[3];
    const float* normal1 = (const float*)d_in[4];
    const float* normal2 = (const float*)d_in[5];
    const float* nres1   = (const float*)d_in[6];
    const float* nres2   = (const float*)d_in[7];
    const float* R12     = (const float*)d_in[8];
    const float* t12     = (const float*)d_in[9];
    const float* R21     = (const float*)d_in[10];
    const float* t21     = (const float*)d_in[11];
    const int*   npts1   = (const int*)d_in[12];
    const int*   npts2   = (const int*)d_in[13];
    float* out = (float*)d_out;

    dim3 bgrid(BB * PP / 256, 2);
    hist_kernel<<<bgrid, 256>>>(xyz1, xyz2, R12, t12, R21, t21, npts1, npts2);
    scan_kernel<<<8, NBIN>>>();
    scatter_kernel<<<bgrid, 256>>>(xyz1, xyz2, R12, t12, R21, t21, npts1, npts2);
    dim3 qgrid(BB * PP / 64, 4);
    query_kernel<<<qgrid, 256>>>(xyz1, hsv1, normal1, nres1,
                                 xyz2, hsv2, normal2, nres2,
                                 R12, t12, R21, t21, npts1, npts2, out);
}

// round 14
// speedup vs baseline: 14.0825x; 1.0750x over previous
#include <cuda_runtime.h>
#include <math.h>

#define BB 2
#define PP 8192
#define KK 20
#define NBIN 128
#define ZLO 1.0f
#define ZSPAN 60.0f
#define INVBINW (NBIN / ZSPAN)
#define BINW (ZSPAN / NBIN)
#define DCAP2 9.0f      // 3 m search-radius cap (dropped terms < 4e-7 each)
#define LBUF 24

__device__ double g_acc[2];            // zero at load; self-cleaned by query_kernel
__device__ unsigned g_done;
__device__ int g_hist[8][NBIN];        // zero at load; self-cleaned by scan_kernel
__device__ int g_offs[8][NBIN + 1];
__device__ int g_curs[8][NBIN];
__device__ float4 g_dbp[4][PP];        // z-binned db points (x,y,z, idx bits)
__device__ float4 g_qp[4][PP];         // z-binned transformed queries

// Insert packed key x into 4 sorted chains of 5 (tails at 4,9,14,19).
#define CHAIN_INSERT(keys, x)                                                   \
    do {                                                                        \
        float tt0 = keys[4], tt1 = keys[9], tt2 = keys[14], tt3 = keys[19];     \
        int sel_ = 0; float bv_ = tt0;                                          \
        if (tt1 > bv_) { bv_ = tt1; sel_ = 1; }                                 \
        if (tt2 > bv_) { bv_ = tt2; sel_ = 2; }                                 \
        if (tt3 > bv_) { bv_ = tt3; sel_ = 3; }                                 \
        float x0_ = (sel_ == 0) ? (x) : 3.3e38f;                                \
        float x1_ = (sel_ == 1) ? (x) : 3.3e38f;                                \
        float x2_ = (sel_ == 2) ? (x) : 3.3e38f;                                \
        float x3_ = (sel_ == 3) ? (x) : 3.3e38f;                                \
        _Pragma("unroll")                                                       \
        for (int k_ = 0; k_ < 5; k_++) {                                        \
            float lo_ = fminf(x0_, keys[k_]); x0_ = fmaxf(x0_, keys[k_]); keys[k_] = lo_; } \
        _Pragma("unroll")                                                       \
        for (int k_ = 5; k_ < 10; k_++) {                                       \
            float lo_ = fminf(x1_, keys[k_]); x1_ = fmaxf(x1_, keys[k_]); keys[k_] = lo_; } \
        _Pragma("unroll")                                                       \
        for (int k_ = 10; k_ < 15; k_++) {                                      \
            float lo_ = fminf(x2_, keys[k_]); x2_ = fmaxf(x2_, keys[k_]); keys[k_] = lo_; } \
        _Pragma("unroll")                                                       \
        for (int k_ = 15; k_ < 20; k_++) {                                      \
            float lo_ = fminf(x3_, keys[k_]); x3_ = fmaxf(x3_, keys[k_]); keys[k_] = lo_; } \
    } while (0)

__device__ __forceinline__ int zbin(float z) {
    return min(NBIN - 1, max(0, (int)floorf((z - ZLO) * INVBINW)));
}

__global__ void hist_kernel(const float* __restrict__ xyz1, const float* __restrict__ xyz2,
                            const float* __restrict__ R12, const float* __restrict__ t12,
                            const float* __restrict__ R21, const float* __restrict__ t21,
                            const int* __restrict__ npts1, const int* __restrict__ npts2) {
    const int s = blockIdx.y;
    const int gi = blockIdx.x * blockDim.x + threadIdx.x;
    const int b = gi >> 13;
    const int i = gi & (PP - 1);
    const int set = s * BB + b;
    const float* dbsrc = s ? xyz1 : xyz2;
    const int ldb = (s ? npts1 : npts2)[b];
    if (i < ldb)
        atomicAdd(&g_hist[set * 2][zbin(dbsrc[3 * gi + 2])], 1);
    const float* qsrc = s ? xyz2 : xyz1;
    const int lq = (s ? npts2 : npts1)[b];
    if (i < lq) {
        const float* Rm = (s ? R21 : R12) + b * 9;
        const float* tv = (s ? t21 : t12) + b * 3;
        float ux = qsrc[3 * gi + 0] - tv[0];
        float uy = qsrc[3 * gi + 1] - tv[1];
        float uz = qsrc[3 * gi + 2] - tv[2];
        float qpz = fmaf(Rm[2], ux, fmaf(Rm[5], uy, Rm[8] * uz));
        atomicAdd(&g_hist[set * 2 + 1][zbin(qpz)], 1);
    }
}

// Parallel scan: one block per histogram array; zeroes g_hist after reading.
__global__ void scan_kernel() {
    __shared__ int sv[NBIN];
    const int a = blockIdx.x;
    const int t = threadIdx.x;
    int v = g_hist[a][t];
    g_hist[a][t] = 0;
    sv[t] = v;
    __syncthreads();
    for (int o = 1; o < NBIN; o <<= 1) {
        int x = (t >= o) ? sv[t - o] : 0;
        __syncthreads();
        sv[t] += x;
        __syncthreads();
    }
    g_offs[a][t + 1] = sv[t];
    g_curs[a][t] = sv[t] - v;
    if (t == 0) g_offs[a][0] = 0;
}

__global__ void scatter_kernel(const float* __restrict__ xyz1, const float* __restrict__ xyz2,
                               const float* __restrict__ R12, const float* __restrict__ t12,
                               const float* __restrict__ R21, const float* __restrict__ t21,
                               const int* __restrict__ npts1, const int* __restrict__ npts2) {
    const int s = blockIdx.y;
    const int gi = blockIdx.x * blockDim.x + threadIdx.x;
    const int b = gi >> 13;
    const int i = gi & (PP - 1);
    const int set = s * BB + b;
    const float* dbsrc = s ? xyz1 : xyz2;
    const int ldb = (s ? npts1 : npts2)[b];
    if (i < ldb) {
        float x = dbsrc[3 * gi + 0], y = dbsrc[3 * gi + 1], z = dbsrc[3 * gi + 2];
        int pos = atomicAdd(&g_curs[set * 2][zbin(z)], 1);
        g_dbp[set][pos] = make_float4(x, y, z, __int_as_float(i));
    }
    const float* qsrc = s ? xyz2 : xyz1;
    const int lq = (s ? npts2 : npts1)[b];
    if (i < lq) {
        const float* Rm = (s ? R21 : R12) + b * 9;
        const float* tv = (s ? t21 : t12) + b * 3;
        float ux = qsrc[3 * gi + 0] - tv[0];
        float uy = qsrc[3 * gi + 1] - tv[1];
        float uz = qsrc[3 * gi + 2] - tv[2];
        float qpx = fmaf(Rm[0], ux, fmaf(Rm[3], uy, Rm[6] * uz));
        float qpy = fmaf(Rm[1], ux, fmaf(Rm[4], uy, Rm[7] * uz));
        float qpz = fmaf(Rm[2], ux, fmaf(Rm[5], uy, Rm[8] * uz));
        int pos = atomicAdd(&g_curs[set * 2 + 1][zbin(qpz)], 1);
        g_qp[set][pos] = make_float4(qpx, qpy, qpz, __int_as_float(i));
    }
}

// 4 warps share 32 z-sorted queries; stride-2 bin walks with a SHARED per-query
// threshold (smem min, monotone -> exact). Chunk-8 distance loop (MLP=8).
// Sub0 merges; epilogue split across all 4 sub-warps (5 winners each).
__global__ __launch_bounds__(256) void query_kernel(
    const float* __restrict__ xyz1, const float* __restrict__ hsv1,
    const float* __restrict__ normal1, const float* __restrict__ nres1,
    const float* __restrict__ xyz2, const float* __restrict__ hsv2,
    const float* __restrict__ normal2, const float* __restrict__ nres2,
    const float* __restrict__ R12, const float* __restrict__ t12,
    const float* __restrict__ R21, const float* __restrict__ t21,
    const int* __restrict__ npts1, const int* __restrict__ npts2,
    float* __restrict__ out)
{
    const int set = blockIdx.y;
    const int s = set >> 1, b = set & 1;
    const int lane = threadIdx.x & 31;
    const int wid = threadIdx.x >> 5;
    const int wgrp = wid >> 2;             // 2 query groups per block
    const int sub = wid & 3;               // 4 walk shards per group
    const int boff = b * PP;

    const float* xq   = s ? xyz2 : xyz1;
    const float* hq   = s ? hsv2 : hsv1;
    const float* nq   = s ? normal2 : normal1;
    const float* rq   = s ? nres2 : nres1;
    const float* xdbr = s ? xyz1 : xyz2;
    const float* ndbr = s ? normal1 : normal2;
    const float* hdb  = s ? hsv1 : hsv2;
    const float* rdb  = s ? nres1 : nres2;
    const float* Rm   = (s ? R21 : R12) + b * 9;
    const int lq = (s ? npts2 : npts1)[b];

    const int base = (blockIdx.x * 2 + wgrp) * 32;
    const int pos = base + lane;
    const bool act = (base < lq) && (pos < lq);

    float4 qr = (base < lq) ? g_qp[set][act ? pos : base]
                            : make_float4(0.f, 0.f, 0.f, __int_as_float(0));
    const float qpx = qr.x, qpy = qr.y, qpz = qr.z;
    const int iq = __float_as_int(qr.w);

    float keys[KK];
#pragma unroll
    for (int k = 0; k < KK; k++) keys[k] = 3.0e38f;
    float sum = 0.f;

    __shared__ float skeys[2][3][32][KK + 1];
    __shared__ float smerged[2][32][KK];
    __shared__ float sthr_sh[2][32];       // shared per-query threshold (min)

    if (sub == 0) sthr_sh[wgrp][lane] = act ? DCAP2 : -1.0f;
    __syncthreads();

    if (base < lq) {
        float thr_l = act ? DCAP2 : -1.0f;
        int cnt = 0;
        unsigned lbuf[LBUF];
        volatile float* vshr = &sthr_sh[wgrp][lane];

        auto compact = [&]() {
            float tail = fmaxf(fmaxf(keys[4], keys[9]), fmaxf(keys[14], keys[19]));
            for (int e = 0; e < cnt; ++e) {
                float xk = __uint_as_float(lbuf[e]);
                if (xk < tail) {
                    CHAIN_INSERT(keys, xk);
                    tail = fmaxf(fmaxf(keys[4], keys[9]), fmaxf(keys[14], keys[19]));
                }
            }
            cnt = 0;
            if (act) {
                float nt = fminf(thr_l, tail * 1.002f);
                float sh = *vshr;                 // other shards' tightenings
                nt = fminf(nt, sh);
                thr_l = nt;
                if (nt < sh) *vshr = nt;          // benign race: monotone min
            }
        };

        const int dbarr = set * 2;
        const float4* __restrict__ dbp = g_dbp[set];

        auto accept = [&](float d2, int j) {
            unsigned key = (__float_as_uint(d2) & 0xFFFFE000u)
                         | (unsigned)__float_as_int(dbp[j].w);
            if (cnt < LBUF) lbuf[cnt++] = key;
            else { float xk = __uint_as_float(key); CHAIN_INSERT(keys, xk); }
        };

        auto procbin = [&](int bin) {
            const int j0 = g_offs[dbarr][bin];
            const int j1 = g_offs[dbarr][bin + 1];
            int j = j0;
            for (; j + 8 <= j1; j += 8) {
                float d2a[8];
#pragma unroll
                for (int u = 0; u < 8; u++) {
                    float4 p = dbp[j + u];
                    float dx = qpx - p.x, dy = qpy - p.y, dz = qpz - p.z;
                    d2a[u] = fmaf(dx, dx, fmaf(dy, dy, dz * dz));
                }
                float m8 = fminf(fminf(fminf(d2a[0], d2a[1]), fminf(d2a[2], d2a[3])),
                                 fminf(fminf(d2a[4], d2a[5]), fminf(d2a[6], d2a[7])));
                if (m8 < thr_l) {
#pragma unroll
                    for (int u = 0; u < 8; u++)
                        if (d2a[u] < thr_l) accept(d2a[u], j + u);
                }
            }
            for (; j < j1; ++j) {
                float4 p = dbp[j];
                float dx = qpx - p.x, dy = qpy - p.y, dz = qpz - p.z;
                float d2 = fmaf(dx, dx, fmaf(dy, dy, dz * dz));
                if (d2 < thr_l) accept(d2, j);
            }
        };

        auto laneneed = [&](int bin) -> bool {
            float loe = ZLO + (float)bin * BINW;
            float hie = loe + BINW;
            float dz = fmaxf(fmaxf(loe - qpz, qpz - hie), 0.f);
            return dz * dz < thr_l;          // false for inactive (thr_l = -1)
        };

        int cb = zbin(qpz);
        int cbm = act ? cb : 0x7fffffff;
        int cbx = act ? cb : (int)0x80000000;
#pragma unroll
        for (int o = 16; o; o >>= 1) {
            cbm = min(cbm, __shfl_xor_sync(0xffffffffu, cbm, o));
            cbx = max(cbx, __shfl_xor_sync(0xffffffffu, cbx, o));
        }
        const int mid = (cbm + cbx) >> 1;

        // Stride-2 walk per sub-warp (monotone in z-distance); per-bin compact
        // refreshes thr (own + shared) before the next stop check.
        int bin  = (sub == 0) ? mid     : (sub == 1) ? mid - 1
                 : (sub == 2) ? mid + 1 : mid + 2;
        const int step = (sub < 2) ? -2 : 2;
        while (bin >= 0 && bin < NBIN) {
            if (!__ballot_sync(0xffffffffu, laneneed(bin))) break;
            procbin(bin);
            compact();
            bin += step;
        }
        compact();
    }

    // Merge: subs 1-3 publish; sub0 folds (guarded) and broadcasts winners.
    if (sub > 0) {
#pragma unroll
        for (int k = 0; k < KK; k++) skeys[wgrp][sub - 1][lane][k] = keys[k];
    }
    __syncthreads();
    if (sub == 0) {
        float tail = fmaxf(fmaxf(keys[4], keys[9]), fmaxf(keys[14], keys[19]));
#pragma unroll
        for (int ws = 0; ws < 3; ws++) {
#pragma unroll
            for (int k = 0; k < KK; k++) {
                float x = skeys[wgrp][ws][lane][k];
                if (x < tail) {
                    CHAIN_INSERT(keys, x);
                    tail = fmaxf(fmaxf(keys[4], keys[9]), fmaxf(keys[14], keys[19]));
                }
            }
        }
#pragma unroll
        for (int k = 0; k < KK; k++) smerged[wgrp][lane][k] = keys[k];
    }
    __syncthreads();

    // Split epilogue: each sub-warp computes 5 of the 20 terms.
    if (act) {
        const int qi = boff + iq;
        const float qz_own = xq[3 * qi + 2];
        float ell = fmaxf(0.015f * (qz_own - 10.0f), 0.15f);
        float inv_ls = 1.0f / (ell * ell);
        float hx = hq[3 * qi + 0], hy = hq[3 * qi + 1], hz = hq[3 * qi + 2];
        float nxr = nq[3 * qi + 0], nyr = nq[3 * qi + 1], nzr = nq[3 * qi + 2];
        float npx = fmaf(Rm[0], nxr, fmaf(Rm[3], nyr, Rm[6] * nzr));
        float npy = fmaf(Rm[1], nxr, fmaf(Rm[4], nyr, Rm[7] * nzr));
        float npz = fmaf(Rm[2], nxr, fmaf(Rm[5], nyr, Rm[8] * nzr));
        float rqv = rq[qi];
#pragma unroll
        for (int k2 = 0; k2 < 5; k2++) {
            float keyv = smerged[wgrp][lane][sub * 5 + k2];
            if (keyv < 1.0e30f) {
                int idx = (int)(__float_as_uint(keyv) & 0x1FFFu);
                int g3 = 3 * (boff + idx);
                float dx = qpx - xdbr[g3 + 0];
                float dy = qpy - xdbr[g3 + 1];
                float dz = qpz - xdbr[g3 + 2];
                float d2 = fmaf(dx, dx, fmaf(dy, dy, dz * dz));
                float ndot = fmaf(npx, ndbr[g3 + 0],
                                  fmaf(npy, ndbr[g3 + 1], npz * ndbr[g3 + 2]));
                float chx = hx - hdb[g3 + 0];
                float chy = hy - hdb[g3 + 1];
                float chz = hz - hdb[g3 + 2];
                float cd = sqrtf(fmaf(chx, chx, fmaf(chy, chy, chz * chz)) + 1e-12f);
                float rk = rdb[boff + idx];
                float alpha = 0.2f / (0.1f + rqv + rk);
                float nk = fmaxf(ndot * alpha, 0.0f);
                sum += __expf(-(d2 * inv_ls + cd * 5.0f)) * nk;
            }
        }
    }

    // Block reduce + single double atomic; last block finalizes + self-cleans.
#pragma unroll
    for (int o = 16; o > 0; o >>= 1) sum += __shfl_down_sync(0xffffffffu, sum, o);
    __shared__ float wsum[8];
    if (lane == 0) wsum[wid] = sum;
    __syncthreads();
    if (threadIdx.x == 0) {
        float bs = 0.f;
#pragma unroll
        for (int w2 = 0; w2 < 8; w2++) bs += wsum[w2];
        atomicAdd(&g_acc[s], (double)bs);
        __threadfence();
        unsigned done = atomicAdd(&g_done, 1u);
        if (done == (unsigned)(gridDim.x * gridDim.y) - 1u) {
            double s1 = (double)npts1[0] + (double)npts1[1];
            double s2 = (double)npts2[0] + (double)npts2[1];
            double k1 = g_acc[0] / (s1 * (double)KK);
            double k2 = g_acc[1] / (s2 * (double)KK);
            out[0] = (float)(0.5 * (k1 + k2));
            g_acc[0] = 0.0;        // self-clean for next replay
            g_acc[1] = 0.0;
            g_done = 0u;
        }
    }
}

extern "C" void kernel_launch(void* const* d_in, const int* in_sizes, int n_in,
                              void* d_out, int out_size) {
    const float* xyz1    = (const float*)d_in[0];
    const float* xyz2    = (const float*)d_in[1];
    const float* hsv1    = (const float*)d_in[2];
    const float* hsv2    = (const float*)d_in[3];
    const float* normal1 = (const float*)d_in[4];
    const float* normal2 = (const float*)d_in[5];
    const float* nres1   = (const float*)d_in[6];
    const float* nres2   = (const float*)d_in[7];
    const float* R12     = (const float*)d_in[8];
    const float* t12     = (const float*)d_in[9];
    const float* R21     = (const float*)d_in[10];
    const float* t21     = (const float*)d_in[11];
    const int*   npts1   = (const int*)d_in[12];
    const int*   npts2   = (const int*)d_in[13];
    float* out = (float*)d_out;

    dim3 bgrid(BB * PP / 256, 2);
    hist_kernel<<<bgrid, 256>>>(xyz1, xyz2, R12, t12, R21, t21, npts1, npts2);
    scan_kernel<<<8, NBIN>>>();
    scatter_kernel<<<bgrid, 256>>>(xyz1, xyz2, R12, t12, R21, t21, npts1, npts2);
    dim3 qgrid(BB * PP / 64, 4);
    query_kernel<<<qgrid, 256>>>(xyz1, hsv1, normal1, nres1,
                                 xyz2, hsv2, normal2, nres2,
                                 R12, t12, R21, t21, npts1, npts2, out);
}